// round 1
// baseline (speedup 1.0000x reference)
#include <cuda_runtime.h>

#define D_MODEL 1024
#define N_HEADS 16
#define DEPTH   64
#define BATCH   2
#define SEQ     2048
#define ROWS    (BATCH*SEQ)

// Scratch (device globals; allocation-free per harness rules)
__device__ float g_Q[ROWS * D_MODEL];
__device__ float g_K[ROWS * D_MODEL];
__device__ float g_V[ROWS * D_MODEL];
__device__ float g_AO[ROWS * D_MODEL];

// ---------------------------------------------------------------------------
// SGEMM + bias: C[M,N] = A[M,K] @ W[K,N] + bias[N]
// 128x128 block tile, BK=8, 8x8 per thread, 256 threads.
// ---------------------------------------------------------------------------
#define BM 128
#define BN 128
#define BK 8
#define TM 8
#define TN 8

__global__ __launch_bounds__(256) void sgemm_bias(
    const float* __restrict__ A, const float* __restrict__ W,
    const float* __restrict__ bias, float* __restrict__ C,
    int M, int N, int K)
{
    __shared__ float As[BK * BM];   // transposed A tile: As[k][m]
    __shared__ float Ws[BK * BN];   // Ws[k][n]

    const int tid = threadIdx.x;
    const int bx = blockIdx.x, by = blockIdx.y;

    const int aRow = tid >> 1;          // 0..127
    const int aCol = (tid & 1) << 2;    // 0 or 4
    const int wRow = tid >> 5;          // 0..7
    const int wCol = (tid & 31) << 2;   // 0..124

    const int tr = (tid >> 4) * TM;     // 0..120
    const int tc = (tid & 15) * TN;     // 0..120

    const float* Ag = A + (size_t)(by * BM) * K;
    const float* Wg = W + bx * BN;

    float acc[TM][TN] = {};

    for (int k0 = 0; k0 < K; k0 += BK) {
        float4 a4 = *(const float4*)(Ag + (size_t)aRow * K + k0 + aCol);
        As[(aCol + 0) * BM + aRow] = a4.x;
        As[(aCol + 1) * BM + aRow] = a4.y;
        As[(aCol + 2) * BM + aRow] = a4.z;
        As[(aCol + 3) * BM + aRow] = a4.w;
        *(float4*)&Ws[wRow * BN + wCol] =
            *(const float4*)(Wg + (size_t)(k0 + wRow) * N + wCol);
        __syncthreads();

        #pragma unroll
        for (int kk = 0; kk < BK; kk++) {
            float ar[TM], wr[TN];
            #pragma unroll
            for (int i = 0; i < TM; i++) ar[i] = As[kk * BM + tr + i];
            #pragma unroll
            for (int j = 0; j < TN; j++) wr[j] = Ws[kk * BN + tc + j];
            #pragma unroll
            for (int i = 0; i < TM; i++)
                #pragma unroll
                for (int j = 0; j < TN; j++)
                    acc[i][j] = fmaf(ar[i], wr[j], acc[i][j]);
        }
        __syncthreads();
    }

    const int crow = by * BM + tr;
    const int ccol = bx * BN + tc;
    #pragma unroll
    for (int i = 0; i < TM; i++) {
        #pragma unroll
        for (int j = 0; j < TN; j += 4) {
            float4 o;
            o.x = acc[i][j + 0] + bias[ccol + j + 0];
            o.y = acc[i][j + 1] + bias[ccol + j + 1];
            o.z = acc[i][j + 2] + bias[ccol + j + 2];
            o.w = acc[i][j + 3] + bias[ccol + j + 3];
            *(float4*)&C[(size_t)(crow + i) * N + ccol + j] = o;
        }
    }
}

// ---------------------------------------------------------------------------
// Flash-attention (fp32, causal, UNSCALED scores).
// Q/K/V stored as [B*S, D_MODEL]; head h occupies columns h*64..h*64+63.
// Block: one (batch, head, 64-row query tile). 256 threads (16x16),
// each thread owns a 4x4 sub-tile of scores and of the 64x64 output.
// Online softmax; key tiles limited to the causal range.
// ---------------------------------------------------------------------------
#define SP 65   // smem row stride (padding -> max 2-way conflicts)

__global__ __launch_bounds__(256) void attn_kernel(
    const float* __restrict__ Qg, const float* __restrict__ Kg,
    const float* __restrict__ Vg, float* __restrict__ Og)
{
    extern __shared__ float sm[];
    float* Qs = sm;                 // [64][SP]
    float* Ks = Qs + 64 * SP;
    float* Vs = Ks + 64 * SP;
    float* Ps = Vs + 64 * SP;

    const int qt = blockIdx.x;          // query tile (0..31)
    const int h  = blockIdx.y;
    const int b  = blockIdx.z;
    const int tid = threadIdx.x;
    const int ty = tid >> 4;            // 0..15 -> rows ty*4..ty*4+3
    const int tx = tid & 15;            // 0..15 -> cols tx*4..tx*4+3

    const size_t base = ((size_t)b * SEQ) * D_MODEL + h * DEPTH;
    const int q0 = qt * 64;

    // Load Q tile (64x64)
    #pragma unroll
    for (int i = 0; i < 4; i++) {
        int idx = tid + i * 256;            // float4 index 0..1023
        int row = idx >> 4;
        int c4  = (idx & 15) << 2;
        float4 v = *(const float4*)&Qg[base + (size_t)(q0 + row) * D_MODEL + c4];
        Qs[row * SP + c4 + 0] = v.x;
        Qs[row * SP + c4 + 1] = v.y;
        Qs[row * SP + c4 + 2] = v.z;
        Qs[row * SP + c4 + 3] = v.w;
    }

    float m[4], l[4], acc[4][4];
    #pragma unroll
    for (int i = 0; i < 4; i++) {
        m[i] = -1e30f; l[i] = 0.f;
        #pragma unroll
        for (int j = 0; j < 4; j++) acc[i][j] = 0.f;
    }

    for (int kt = 0; kt <= qt; kt++) {
        __syncthreads();   // protect Qs (first iter) / Vs,Ps (later iters)
        const int k0 = kt * 64;
        #pragma unroll
        for (int i = 0; i < 4; i++) {
            int idx = tid + i * 256;
            int row = idx >> 4;
            int c4  = (idx & 15) << 2;
            float4 kv = *(const float4*)&Kg[base + (size_t)(k0 + row) * D_MODEL + c4];
            float4 vv = *(const float4*)&Vg[base + (size_t)(k0 + row) * D_MODEL + c4];
            Ks[row * SP + c4 + 0] = kv.x; Ks[row * SP + c4 + 1] = kv.y;
            Ks[row * SP + c4 + 2] = kv.z; Ks[row * SP + c4 + 3] = kv.w;
            Vs[row * SP + c4 + 0] = vv.x; Vs[row * SP + c4 + 1] = vv.y;
            Vs[row * SP + c4 + 2] = vv.z; Vs[row * SP + c4 + 3] = vv.w;
        }
        __syncthreads();

        // Scores: S[4][4] = Q rows (ty*4+i) . K rows (tx*4+j), over d=64
        float s[4][4];
        #pragma unroll
        for (int i = 0; i < 4; i++)
            #pragma unroll
            for (int j = 0; j < 4; j++) s[i][j] = 0.f;

        #pragma unroll 8
        for (int d = 0; d < 64; d++) {
            float qr[4], kr[4];
            #pragma unroll
            for (int i = 0; i < 4; i++) qr[i] = Qs[(ty * 4 + i) * SP + d];
            #pragma unroll
            for (int j = 0; j < 4; j++) kr[j] = Ks[(tx * 4 + j) * SP + d];
            #pragma unroll
            for (int i = 0; i < 4; i++)
                #pragma unroll
                for (int j = 0; j < 4; j++)
                    s[i][j] = fmaf(qr[i], kr[j], s[i][j]);
        }

        if (kt == qt) {  // causal mask only on the diagonal tile
            #pragma unroll
            for (int i = 0; i < 4; i++)
                #pragma unroll
                for (int j = 0; j < 4; j++)
                    if (tx * 4 + j > ty * 4 + i) s[i][j] = -1e30f;
        }

        // Online softmax (row groups of 16 lanes: shfl_xor widths 1,2,4,8)
        #pragma unroll
        for (int i = 0; i < 4; i++) {
            float rm = fmaxf(fmaxf(s[i][0], s[i][1]), fmaxf(s[i][2], s[i][3]));
            #pragma unroll
            for (int off = 1; off < 16; off <<= 1)
                rm = fmaxf(rm, __shfl_xor_sync(0xffffffffu, rm, off));
            float mn = fmaxf(m[i], rm);
            float corr = __expf(m[i] - mn);
            m[i] = mn;
            float rs = 0.f;
            #pragma unroll
            for (int j = 0; j < 4; j++) {
                float p = __expf(s[i][j] - mn);
                s[i][j] = p;
                rs += p;
            }
            #pragma unroll
            for (int off = 1; off < 16; off <<= 1)
                rs += __shfl_xor_sync(0xffffffffu, rs, off);
            l[i] = l[i] * corr + rs;
            #pragma unroll
            for (int j = 0; j < 4; j++) {
                acc[i][j] *= corr;
                Ps[(ty * 4 + i) * SP + tx * 4 + j] = s[i][j];
            }
        }
        __syncthreads();

        // O += P @ V   (thread owns rows ty*4.., depth cols tx*4..)
        #pragma unroll 8
        for (int c = 0; c < 64; c++) {
            float pr[4], vv[4];
            #pragma unroll
            for (int i = 0; i < 4; i++) pr[i] = Ps[(ty * 4 + i) * SP + c];
            #pragma unroll
            for (int j = 0; j < 4; j++) vv[j] = Vs[c * SP + tx * 4 + j];
            #pragma unroll
            for (int i = 0; i < 4; i++)
                #pragma unroll
                for (int j = 0; j < 4; j++)
                    acc[i][j] = fmaf(pr[i], vv[j], acc[i][j]);
        }
    }

    // Normalize and write out in [b, s, h*64+d] layout
    #pragma unroll
    for (int i = 0; i < 4; i++) {
        float inv = 1.f / l[i];
        float4 o;
        o.x = acc[i][0] * inv;
        o.y = acc[i][1] * inv;
        o.z = acc[i][2] * inv;
        o.w = acc[i][3] * inv;
        *(float4*)&Og[base + (size_t)(q0 + ty * 4 + i) * D_MODEL + tx * 4] = o;
    }
}

// ---------------------------------------------------------------------------
// Launch
// ---------------------------------------------------------------------------
extern "C" void kernel_launch(void* const* d_in, const int* in_sizes, int n_in,
                              void* d_out, int out_size)
{
    const float* q  = (const float*)d_in[0];
    const float* k  = (const float*)d_in[1];
    const float* v  = (const float*)d_in[2];
    const float* wq = (const float*)d_in[3];
    const float* bq = (const float*)d_in[4];
    const float* wk = (const float*)d_in[5];
    const float* bk = (const float*)d_in[6];
    const float* wv = (const float*)d_in[7];
    const float* bv = (const float*)d_in[8];
    const float* wo = (const float*)d_in[9];
    const float* bo = (const float*)d_in[10];
    float* out = (float*)d_out;

    float *Qb, *Kb, *Vb, *AOb;
    cudaGetSymbolAddress((void**)&Qb,  g_Q);
    cudaGetSymbolAddress((void**)&Kb,  g_K);
    cudaGetSymbolAddress((void**)&Vb,  g_V);
    cudaGetSymbolAddress((void**)&AOb, g_AO);

    dim3 ggrid(D_MODEL / BN, ROWS / BM);   // (8, 32)
    sgemm_bias<<<ggrid, 256>>>(q, wq, bq, Qb, ROWS, D_MODEL, D_MODEL);
    sgemm_bias<<<ggrid, 256>>>(k, wk, bk, Kb, ROWS, D_MODEL, D_MODEL);
    sgemm_bias<<<ggrid, 256>>>(v, wv, bv, Vb, ROWS, D_MODEL, D_MODEL);

    const int smem = 4 * 64 * SP * (int)sizeof(float);  // 66560 B
    cudaFuncSetAttribute(attn_kernel,
                         cudaFuncAttributeMaxDynamicSharedMemorySize, smem);
    dim3 agrid(SEQ / 64, N_HEADS, BATCH);  // (32, 16, 2)
    attn_kernel<<<agrid, 256, smem>>>(Qb, Kb, Vb, AOb);

    sgemm_bias<<<ggrid, 256>>>(AOb, wo, bo, out, ROWS, D_MODEL, D_MODEL);
}